// round 2
// baseline (speedup 1.0000x reference)
#include <cuda_runtime.h>

// Problem dims (fixed by the dataset)
constexpr int L = 13;
constexpr int B = 16;
constexpr int S = 512;
constexpr int D = 768;
constexpr int W = 256;
constexpr int D4 = D / 4;          // 192 float4 per row

// Scratch: word-span starts per sentence. starts[b][w] = first s with seg[b,s] >= w.
// starts[b][W] = S. Size B*(W+1) ints — tiny.
__device__ int g_starts[B * (W + 1)];

// Kernel A: compute spans via binary search over the sorted segment ids.
__global__ void compute_starts_kernel(const int* __restrict__ seg) {
    int idx = blockIdx.x * blockDim.x + threadIdx.x;
    if (idx >= B * (W + 1)) return;
    int b = idx / (W + 1);
    int w = idx % (W + 1);
    const int* row = seg + b * S;
    // lower_bound: count of elements < w
    int lo = 0, hi = S;
    while (lo < hi) {
        int mid = (lo + hi) >> 1;
        if (row[mid] < w) lo = mid + 1;
        else hi = mid;
    }
    g_starts[idx] = lo;
}

// Kernel B: one thread per output float4. out[l,b,w, d4] = sum over span.
__global__ void __launch_bounds__(256) segment_sum_kernel(
    const float4* __restrict__ hidden,   // [L,B,S,D4]
    float4* __restrict__ out             // [L,B,W,D4]
) {
    int idx = blockIdx.x * blockDim.x + threadIdx.x;   // == output float4 index
    // total = L*B*W*D4 = 10,223,616; grid sized exactly, no bounds check needed
    int d4 = idx % D4;
    int w_lin = idx / D4;          // l*B*W + b*W + w
    int w = w_lin % W;
    int bl = w_lin / W;            // l*B + b
    int b = bl % B;

    int s0 = g_starts[b * (W + 1) + w];
    int s1 = g_starts[b * (W + 1) + w + 1];

    const float4* src = hidden + ((long long)bl * S + s0) * D4 + d4;
    float4 acc = make_float4(0.f, 0.f, 0.f, 0.f);
    for (int s = s0; s < s1; ++s) {
        float4 v = *src;
        acc.x += v.x; acc.y += v.y; acc.z += v.z; acc.w += v.w;
        src += D4;
    }
    out[idx] = acc;
}

extern "C" void kernel_launch(void* const* d_in, const int* in_sizes, int n_in,
                              void* d_out, int out_size) {
    const float* hidden = (const float*)d_in[0];
    const int* seg = (const int*)d_in[1];
    // d_in[2] = num_words (scalar) — W is hardcoded.

    {
        int total = B * (W + 1);
        int threads = 256;
        compute_starts_kernel<<<(total + threads - 1) / threads, threads>>>(seg);
    }
    {
        long long total = (long long)L * B * W * D4;   // 10,223,616 — divisible by 256
        int threads = 256;
        int blocks = (int)(total / threads);
        segment_sum_kernel<<<blocks, threads>>>(
            (const float4*)hidden, (float4*)d_out);
    }
}

// round 5
// speedup vs baseline: 1.0387x; 1.0387x over previous
#include <cuda_runtime.h>

// Problem dims (fixed by the dataset)
constexpr int L = 13;
constexpr int B = 16;
constexpr int S = 512;
constexpr int D = 768;
constexpr int W = 256;
constexpr int D4 = D / 4;          // 192 float4 per row
constexpr int HALF = D4 / 2;       // 96: each thread handles cols c and c+96

// One fused kernel. One thread per PAIR of output float4s.
// Total threads = L*B*W*HALF = 5,111,808 = 19968 blocks * 256.
__global__ void __launch_bounds__(256) segment_sum_fused(
    const float4* __restrict__ hidden,   // [L,B,S,D4]
    const int*    __restrict__ seg,      // [B,S] sorted per row
    float4*       __restrict__ out       // [L,B,W,D4]
) {
    int idx = blockIdx.x * blockDim.x + threadIdx.x;
    int c     = idx % HALF;          // column 0..95
    int row   = idx / HALF;          // l*B*W + b*W + w
    int w     = row % W;
    int bl    = row / W;             // l*B + b
    int b     = bl % B;

    // Span via two lower_bounds over the sorted seg row. All 32 lanes of a
    // warp share (b,w) -> identical control flow, broadcast L1 loads.
    // NOTE: full while-loops — a fixed 9-iter unroll is one short for S=512.
    const int* srow = seg + b * S;
    int s0, s1;
    {
        int lo = 0, hi = S;
        while (lo < hi) {
            int mid = (lo + hi) >> 1;
            if (__ldg(srow + mid) < w) lo = mid + 1; else hi = mid;
        }
        s0 = lo;
        int w1 = w + 1;
        lo = s0; hi = S;             // lower_bound(w+1) >= lower_bound(w)
        while (lo < hi) {
            int mid = (lo + hi) >> 1;
            if (__ldg(srow + mid) < w1) lo = mid + 1; else hi = mid;
        }
        s1 = lo;
    }

    const float4* src = hidden + ((long long)bl * S + s0) * D4 + c;
    float4 acc0 = make_float4(0.f, 0.f, 0.f, 0.f);
    float4 acc1 = make_float4(0.f, 0.f, 0.f, 0.f);
    for (int s = s0; s < s1; ++s) {
        // two independent 16B loads in flight per iteration (MLP=2)
        float4 v0 = __ldg(src);
        float4 v1 = __ldg(src + HALF);
        acc0.x += v0.x; acc0.y += v0.y; acc0.z += v0.z; acc0.w += v0.w;
        acc1.x += v1.x; acc1.y += v1.y; acc1.z += v1.z; acc1.w += v1.w;
        src += D4;
    }

    float4* dst = out + (long long)row * D4 + c;
    dst[0]    = acc0;
    dst[HALF] = acc1;
}

extern "C" void kernel_launch(void* const* d_in, const int* in_sizes, int n_in,
                              void* d_out, int out_size) {
    const float* hidden = (const float*)d_in[0];
    const int*   seg    = (const int*)d_in[1];
    // d_in[2] = num_words scalar — W hardcoded.

    long long total = (long long)L * B * W * HALF;   // 5,111,808
    int threads = 256;
    int blocks = (int)(total / threads);             // 19968 exactly
    segment_sum_fused<<<blocks, threads>>>(
        (const float4*)hidden, seg, (float4*)d_out);
}